// round 12
// baseline (speedup 1.0000x reference)
#include <cuda_runtime.h>
#include <cuda_bf16.h>
#include <math.h>

#define NTOK   8192
#define NPAIR  (NTOK * 2)
#define NE     64
#define TPB    16
#define MAXCHUNK (NPAIR / TPB + NE)   // 1088

// ---- scratch (device globals; no allocs allowed) ----
__device__ float g_h[(size_t)NTOK * 4096];        // 134 MB
__device__ float g_yup[(size_t)NPAIR * 4096];     // 268 MB
__device__ float g_ydown[(size_t)NPAIR * 1024];   // 67 MB
__device__ float g_logits[(size_t)NTOK * NE];     // 2 MB
__device__ float g_logits2[(size_t)NTOK * NE];    // 2 MB (K-split partial)
__device__ float g_prob[NPAIR];
__device__ int   g_cnt[NE];
__device__ int   g_list[NE * NPAIR];              // 4 MB
__device__ int2  g_chunk[MAXCHUNK];
__device__ int   g_nchunks;

__device__ __forceinline__ float gelu_erf(float v) { return v * normcdff(v); }

// split fp32 into bf16 hi + bf16 lo (v ~= hi + lo, |resid| <~ 2^-18 |v|)
__device__ __forceinline__ void split_bf16(float v, __nv_bfloat16& h, __nv_bfloat16& l) {
    h = __float2bfloat16_rn(v);
    l = __float2bfloat16_rn(v - __bfloat162float(h));
}

// one m16n8k16 bf16 mma, fp32 accumulate (in place)
__device__ __forceinline__ void mma_bf16(float* d, const unsigned* a, const unsigned* b) {
    asm volatile(
        "mma.sync.aligned.m16n8k16.row.col.f32.bf16.bf16.f32 "
        "{%0,%1,%2,%3}, {%4,%5,%6,%7}, {%8,%9}, {%0,%1,%2,%3};"
        : "+f"(d[0]), "+f"(d[1]), "+f"(d[2]), "+f"(d[3])
        : "r"(a[0]), "r"(a[1]), "r"(a[2]), "r"(a[3]), "r"(b[0]), "r"(b[1]));
}

// ---------------------------------------------------------------------------
// Up router GEMM (fp32-exact SIMT): logits = X W^T, 64-token tiles.
// ---------------------------------------------------------------------------
__global__ __launch_bounds__(256) void router_up(
    const float* __restrict__ X, const float* __restrict__ W,
    float* __restrict__ out0)
{
    __shared__ __align__(16) float sX[64][33];    // [m][k] scalar distinct reads
    __shared__ __align__(16) float sWT[32][68];   // [k][e] uniform float4 reads
    const int tid  = threadIdx.x;
    const int lane = tid & 31;
    const int warp = tid >> 5;
    if (blockIdx.x == 0 && tid < NE) g_cnt[tid] = 0;   // reset for top2

    const int m0 = blockIdx.x * 64;
    const int eb = warp * 8;

    float acc[2][8];
    #pragma unroll
    for (int i = 0; i < 2; i++)
        #pragma unroll
        for (int j = 0; j < 8; j++) acc[i][j] = 0.f;

    for (int kc = 0; kc < 1024; kc += 32) {
        #pragma unroll
        for (int rr = 0; rr < 2; rr++) {
            int f = tid + 256 * rr;
            int m = f >> 3, kl = (f & 7) * 4;
            float4 v = __ldg((const float4*)&X[(size_t)(m0 + m) * 1024 + kc + kl]);
            sX[m][kl] = v.x; sX[m][kl+1] = v.y; sX[m][kl+2] = v.z; sX[m][kl+3] = v.w;
        }
        #pragma unroll
        for (int rr = 0; rr < 2; rr++) {
            int f = tid + 256 * rr;
            int e = f >> 3, kl = (f & 7) * 4;
            float4 v = __ldg((const float4*)&W[(size_t)e * 1024 + kc + kl]);
            sWT[kl][e] = v.x; sWT[kl+1][e] = v.y; sWT[kl+2][e] = v.z; sWT[kl+3][e] = v.w;
        }
        __syncthreads();
        #pragma unroll
        for (int k = 0; k < 32; k++) {
            float x0 = sX[lane][k];
            float x1 = sX[lane + 32][k];
            float4 wa = *(const float4*)&sWT[k][eb];
            float4 wb = *(const float4*)&sWT[k][eb + 4];
            acc[0][0] += x0*wa.x; acc[0][1] += x0*wa.y; acc[0][2] += x0*wa.z; acc[0][3] += x0*wa.w;
            acc[0][4] += x0*wb.x; acc[0][5] += x0*wb.y; acc[0][6] += x0*wb.z; acc[0][7] += x0*wb.w;
            acc[1][0] += x1*wa.x; acc[1][1] += x1*wa.y; acc[1][2] += x1*wa.z; acc[1][3] += x1*wa.w;
            acc[1][4] += x1*wb.x; acc[1][5] += x1*wb.y; acc[1][6] += x1*wb.z; acc[1][7] += x1*wb.w;
        }
        __syncthreads();
    }
    #pragma unroll
    for (int mm = 0; mm < 2; mm++) {
        float* lg = &out0[(size_t)(m0 + lane + 32 * mm) * NE + eb];
        *(float4*)lg       = make_float4(acc[mm][0], acc[mm][1], acc[mm][2], acc[mm][3]);
        *(float4*)(lg + 4) = make_float4(acc[mm][4], acc[mm][5], acc[mm][6], acc[mm][7]);
    }
}

// ---------------------------------------------------------------------------
// Down router, FUSED with combine_up: stages h = gelu(s*(p0*y0+p1*y1)+bias)
// on the fly (identical arithmetic/order to the old combine_up), uses it for
// the logits GEMM tile, and writes it once to g_h (K-split parts disjoint).
// Grid = 2 * 128 blocks: part = bid>>7 covers k in [part*2048, part*2048+2048).
// ---------------------------------------------------------------------------
__global__ __launch_bounds__(256) void router_down_fused(
    const float* __restrict__ W,
    const float* __restrict__ scale, const float* __restrict__ bias,
    float* __restrict__ out0, float* __restrict__ out1)
{
    __shared__ __align__(16) float sX[64][33];    // [m][k] = h tile
    __shared__ __align__(16) float sWT[32][68];   // [k][e]
    const int tid  = threadIdx.x;
    const int lane = tid & 31;
    const int warp = tid >> 5;
    if (blockIdx.x == 0 && tid < NE) g_cnt[tid] = 0;   // reset for down top2

    const int part  = blockIdx.x >> 7;
    const int bx    = blockIdx.x & 127;
    const int k_off = part * 2048;
    float* outp     = part ? out1 : out0;

    const int m0 = bx * 64;
    const int eb = warp * 8;
    const float s = __ldg(scale);

    float acc[2][8];
    #pragma unroll
    for (int i = 0; i < 2; i++)
        #pragma unroll
        for (int j = 0; j < 8; j++) acc[i][j] = 0.f;

    for (int kc = 0; kc < 2048; kc += 32) {
        // stage h tile: compute gelu-combine inline, keep in smem + write g_h
        #pragma unroll
        for (int rr = 0; rr < 2; rr++) {
            int f  = tid + 256 * rr;
            int m  = f >> 3, kl = (f & 7) * 4;
            int t  = m0 + m;
            int k  = k_off + kc + kl;
            float4 a  = __ldg((const float4*)&g_yup[(size_t)(2 * t) * 4096 + k]);
            float4 c  = __ldg((const float4*)&g_yup[(size_t)(2 * t + 1) * 4096 + k]);
            float4 bb = __ldg((const float4*)&bias[k]);
            float p0 = g_prob[2 * t], p1 = g_prob[2 * t + 1];
            float4 v;
            v.x = gelu_erf(s * (p0 * a.x + p1 * c.x) + bb.x);
            v.y = gelu_erf(s * (p0 * a.y + p1 * c.y) + bb.y);
            v.z = gelu_erf(s * (p0 * a.z + p1 * c.z) + bb.z);
            v.w = gelu_erf(s * (p0 * a.w + p1 * c.w) + bb.w);
            sX[m][kl] = v.x; sX[m][kl+1] = v.y; sX[m][kl+2] = v.z; sX[m][kl+3] = v.w;
            *(float4*)&g_h[(size_t)t * 4096 + k] = v;
        }
        // stage W transposed
        #pragma unroll
        for (int rr = 0; rr < 2; rr++) {
            int f = tid + 256 * rr;
            int e = f >> 3, kl = (f & 7) * 4;
            float4 v = __ldg((const float4*)&W[(size_t)e * 4096 + k_off + kc + kl]);
            sWT[kl][e] = v.x; sWT[kl+1][e] = v.y; sWT[kl+2][e] = v.z; sWT[kl+3][e] = v.w;
        }
        __syncthreads();
        #pragma unroll
        for (int k = 0; k < 32; k++) {
            float x0 = sX[lane][k];
            float x1 = sX[lane + 32][k];
            float4 wa = *(const float4*)&sWT[k][eb];
            float4 wb = *(const float4*)&sWT[k][eb + 4];
            acc[0][0] += x0*wa.x; acc[0][1] += x0*wa.y; acc[0][2] += x0*wa.z; acc[0][3] += x0*wa.w;
            acc[0][4] += x0*wb.x; acc[0][5] += x0*wb.y; acc[0][6] += x0*wb.z; acc[0][7] += x0*wb.w;
            acc[1][0] += x1*wa.x; acc[1][1] += x1*wa.y; acc[1][2] += x1*wa.z; acc[1][3] += x1*wa.w;
            acc[1][4] += x1*wb.x; acc[1][5] += x1*wb.y; acc[1][6] += x1*wb.z; acc[1][7] += x1*wb.w;
        }
        __syncthreads();
    }
    #pragma unroll
    for (int mm = 0; mm < 2; mm++) {
        float* lg = &outp[(size_t)(m0 + lane + 32 * mm) * NE + eb];
        *(float4*)lg       = make_float4(acc[mm][0], acc[mm][1], acc[mm][2], acc[mm][3]);
        *(float4*)(lg + 4) = make_float4(acc[mm][4], acc[mm][5], acc[mm][6], acc[mm][7]);
    }
}

// ---------------------------------------------------------------------------
// Top-2 + softmax + per-expert list build.
// ---------------------------------------------------------------------------
__global__ __launch_bounds__(256) void top2_kernel(
    const float* __restrict__ lg1, const float* __restrict__ lg2)
{
    const int t    = blockIdx.x * 8 + (threadIdx.x >> 5);
    const int lane = threadIdx.x & 31;
    float v0 = lg1[(size_t)t * NE + lane];
    float v1 = lg1[(size_t)t * NE + lane + 32];
    if (lg2) {
        v0 += lg2[(size_t)t * NE + lane];
        v1 += lg2[(size_t)t * NE + lane + 32];
    }

    float m1; int i1;
    if (v0 >= v1) { m1 = v0; i1 = lane; } else { m1 = v1; i1 = lane + 32; }
    #pragma unroll
    for (int off = 16; off > 0; off >>= 1) {
        float om = __shfl_xor_sync(0xffffffffu, m1, off);
        int   oi = __shfl_xor_sync(0xffffffffu, i1, off);
        if (om > m1 || (om == m1 && oi < i1)) { m1 = om; i1 = oi; }
    }
    float c0 = (lane == i1)      ? -INFINITY : v0;
    float c1 = (lane + 32 == i1) ? -INFINITY : v1;
    float m2; int i2;
    if (c0 >= c1) { m2 = c0; i2 = lane; } else { m2 = c1; i2 = lane + 32; }
    #pragma unroll
    for (int off = 16; off > 0; off >>= 1) {
        float om = __shfl_xor_sync(0xffffffffu, m2, off);
        int   oi = __shfl_xor_sync(0xffffffffu, i2, off);
        if (om > m2 || (om == m2 && oi < i2)) { m2 = om; i2 = oi; }
    }
    if (lane == 0) {
        float p1 = 1.f / (1.f + expf(m2 - m1));
        g_prob[2 * t]     = p1;
        g_prob[2 * t + 1] = 1.f - p1;
        int pos = atomicAdd(&g_cnt[i1], 1);
        g_list[i1 * NPAIR + pos] = 2 * t;
        pos = atomicAdd(&g_cnt[i2], 1);
        g_list[i2 * NPAIR + pos] = 2 * t + 1;
    }
}

__global__ void prefix_kernel()
{
    __shared__ int s_c[NE];
    __shared__ int s_off[NE];
    const int e = threadIdx.x;
    int c = (g_cnt[e] + TPB - 1) / TPB;
    s_c[e] = c;
    __syncthreads();
    if (e == 0) {
        int s = 0;
        for (int i = 0; i < NE; i++) { s_off[i] = s; s += s_c[i]; }
        g_nchunks = s;
    }
    __syncthreads();
    int o = s_off[e];
    for (int i = 0; i < c; i++)
        g_chunk[o + i] = make_int2(e, i * TPB);
}

// ---------------------------------------------------------------------------
// Up bilinear, bf16 3-product (R10, passing).
// ---------------------------------------------------------------------------
__global__ __launch_bounds__(256) void bilinear_up(
    const float* __restrict__ x, const float* __restrict__ A, const float* __restrict__ B)
{
    const int b = blockIdx.x;
    if (b >= g_nchunks) return;
    const int2 ch   = g_chunk[b];
    const int e     = ch.x;
    const int start = ch.y;
    const int cnt   = g_cnt[e];
    const int tid   = threadIdx.x;
    const int lane  = tid & 31;
    const int warp  = tid >> 5;
    const int gid   = lane >> 2;    // 0..7
    const int tig   = lane & 3;     // 0..3

    __shared__ __align__(16) __nv_bfloat16 sA[64][72];     // A-op: [o][ihi 0-31 | ilo 36-67]
    __shared__ __align__(16) __nv_bfloat16 sB[64][72];     // B-op: [p][jhi | jlo]
    __shared__ __align__(16) __nv_bfloat16 sXT[2][32][72]; // B-op: [j][ihi | ilo]  (X^T)
    __shared__ __align__(16) __nv_bfloat16 sT[2][64][72];  // A-op: [o][jhi | jlo]

    // stage A_up[e] (64x32) and B_up[e] (64x32) hi/lo
    {
        const float4* a4 = (const float4*)(A + (size_t)e * 2048);
        const float4* b4 = (const float4*)(B + (size_t)e * 2048);
        #pragma unroll
        for (int rr = 0; rr < 2; rr++) {
            int f = tid + 256 * rr;
            int row = f >> 3, c0 = (f & 7) * 4;
            float4 av = __ldg(&a4[f]);
            float4 bv = __ldg(&b4[f]);
            float aa[4] = {av.x, av.y, av.z, av.w};
            float bb[4] = {bv.x, bv.y, bv.z, bv.w};
            #pragma unroll
            for (int q = 0; q < 4; q++) {
                __nv_bfloat16 h, l;
                split_bf16(aa[q], h, l);
                sA[row][c0 + q] = h; sA[row][36 + c0 + q] = l;
                split_bf16(bb[q], h, l);
                sB[row][c0 + q] = h; sB[row][36 + c0 + q] = l;
            }
        }
    }

    const int pl = warp >> 2;      // local pair 0/1
    const int mt = warp & 3;       // m-tile
    const int R  = mt * 16;

    for (int u = 0; u < TPB; u += 2) {
        int pi0 = start + u;
        if (pi0 >= cnt) break;                 // block-uniform
        int  pair0  = g_list[e * NPAIR + pi0];
        bool valid1 = (pi0 + 1 < cnt);
        int  pair1  = valid1 ? g_list[e * NPAIR + pi0 + 1] : pair0;
        const int myPair = pl ? pair1 : pair0;
        const bool myValid = (pl == 0) || valid1;

        // ---- stage X^T hi/lo for both pairs ----
        {
            int ts[2] = {pair0 >> 1, pair1 >> 1};
            int i = tid >> 3, j0 = (tid & 7) * 4;
            #pragma unroll
            for (int pp = 0; pp < 2; pp++) {
                float4 xv = __ldg((const float4*)&x[(size_t)ts[pp] * 1024 + tid * 4]);
                float vv[4] = {xv.x, xv.y, xv.z, xv.w};
                #pragma unroll
                for (int q = 0; q < 4; q++) {
                    __nv_bfloat16 h, l;
                    split_bf16(vv[q], h, l);
                    sXT[pp][j0 + q][i]      = h;
                    sXT[pp][j0 + q][36 + i] = l;
                }
            }
        }
        __syncthreads();

        // ---- T phase: D[64,32], 2 k-chunks x 3 products ----
        {
            float d[4][4];
            #pragma unroll
            for (int nt = 0; nt < 4; nt++)
                #pragma unroll
                for (int q = 0; q < 4; q++) d[nt][q] = 0.f;
            #pragma unroll
            for (int kc = 0; kc < 2; kc++) {
                const int ac = kc * 16 + 2 * tig;
                unsigned ah[4], al[4];
                ah[0] = *(const unsigned*)&sA[R + gid][ac];
                ah[1] = *(const unsigned*)&sA[R + gid + 8][ac];
                ah[2] = *(const unsigned*)&sA[R + gid][ac + 8];
                ah[3] = *(const unsigned*)&sA[R + gid + 8][ac + 8];
                al[0] = *(const unsigned*)&sA[R + gid][ac + 36];
                al[1] = *(const unsigned*)&sA[R + gid + 8][ac + 36];
                al[2] = *(const unsigned*)&sA[R + gid][ac + 44];
                al[3] = *(const unsigned*)&sA[R + gid + 8][ac + 44];
                #pragma unroll
                for (int nt = 0; nt < 4; nt++) {
                    const __nv_bfloat16* xr = sXT[pl][nt * 8 + gid];
                    unsigned bh[2], bl[2];
                    bh[0] = *(const unsigned*)&xr[ac];
                    bh[1] = *(const unsigned*)&xr[ac + 8];
                    bl[0] = *(const unsigned*)&xr[ac + 36];
                    bl[1] = *(const unsigned*)&xr[ac + 44];
                    mma_bf16(d[nt], ah, bh);
                    mma_bf16(d[nt], al, bh);
                    mma_bf16(d[nt], ah, bl);
                }
            }
            // store T hi/lo
            #pragma unroll
            for (int nt = 0; nt < 4; nt++) {
                int col = nt * 8 + 2 * tig;
                __nv_bfloat16 h0, l0, h1, l1;
                split_bf16(d[nt][0], h0, l0);
                split_bf16(d[nt][1], h1, l1);
                *(__nv_bfloat162*)&sT[pl][R + gid][col]      = __halves2bfloat162(h0, h1);
                *(__nv_bfloat162*)&sT[pl][R + gid][col + 36] = __halves2bfloat162(l0, l1);
                split_bf16(d[nt][2], h0, l0);
                split_bf16(d[nt][3], h1, l1);
                *(__nv_bfloat162*)&sT[pl][R + gid + 8][col]      = __halves2bfloat162(h0, h1);
                *(__nv_bfloat162*)&sT[pl][R + gid + 8][col + 36] = __halves2bfloat162(l0, l1);
            }
        }
        __syncthreads();

        // ---- Y phase: D[64,64], 2 k-chunks x 3 products ----
        {
            float y[8][4];
            #pragma unroll
            for (int nt = 0; nt < 8; nt++)
                #pragma unroll
                for (int q = 0; q < 4; q++) y[nt][q] = 0.f;
            #pragma unroll
            for (int kc = 0; kc < 2; kc++) {
                const int ac = kc * 16 + 2 * tig;
                unsigned ah[4], al[4];
                ah[0] = *(const unsigned*)&sT[pl][R + gid][ac];
                ah[1] = *(const unsigned*)&sT[pl][R + gid + 8][ac];
                ah[2] = *(const unsigned*)&sT[pl][R + gid][ac + 8];
                ah[3] = *(const unsigned*)&sT[pl][R + gid + 8][ac + 8];
                al[0] = *(const unsigned*)&sT[pl][R + gid][ac + 36];
                al[1] = *(const unsigned*)&sT[pl][R + gid + 8][ac + 36];
                al[2] = *(const unsigned*)&sT[pl][R + gid][ac + 44];
                al[3] = *(const unsigned*)&sT[pl][R + gid + 8][ac + 44];
                #pragma unroll
                for (int nt = 0; nt < 8; nt++) {
                    const __nv_bfloat16* br = sB[nt * 8 + gid];
                    unsigned bh[2], bl[2];
                    bh[0] = *(const unsigned*)&br[ac];
                    bh[1] = *(const unsigned*)&br[ac + 8];
                    bl[0] = *(const unsigned*)&br[ac + 36];
                    bl[1] = *(const unsigned*)&br[ac + 44];
                    mma_bf16(y[nt], ah, bh);
                    mma_bf16(y[nt], al, bh);
                    mma_bf16(y[nt], ah, bl);
                }
            }
            if (myValid) {
                float* yo = &g_yup[(size_t)myPair * 4096];
                #pragma unroll
                for (int nt = 0; nt < 8; nt++) {
                    int col = nt * 8 + 2 * tig;
                    *(float2*)&yo[(R + gid) * 64 + col]     = make_float2(y[nt][0], y[nt][1]);
                    *(float2*)&yo[(R + gid + 8) * 64 + col] = make_float2(y[nt][2], y[nt][3]);
                }
            }
        }
        __syncthreads();
    }
}

// ---------------------------------------------------------------------------
// Down bilinear, bf16 3-product (R10, passing).
// ---------------------------------------------------------------------------
__global__ __launch_bounds__(256) void bilinear_down(
    const float* __restrict__ A, const float* __restrict__ B)
{
    const int b = blockIdx.x;
    if (b >= g_nchunks) return;
    const int2 ch   = g_chunk[b];
    const int e     = ch.x;
    const int start = ch.y;
    const int cnt   = g_cnt[e];
    const int tid   = threadIdx.x;
    const int lane  = tid & 31;
    const int warp  = tid >> 5;
    const int gid   = lane >> 2;
    const int tig   = lane & 3;

    __shared__ __align__(16) __nv_bfloat16 sA[32][136];   // A-op: [o][ihi 0-63 | ilo 68-131]
    __shared__ __align__(16) __nv_bfloat16 sB[32][136];   // B-op: [p][jhi | jlo]
    __shared__ __align__(16) __nv_bfloat16 sHT[64][136];  // B-op: [j][ihi | ilo]  (H^T)
    __shared__ __align__(16) __nv_bfloat16 sT[32][136];   // A-op: [o][jhi | jlo]

    // stage A_down[e] (32x64), B_down[e] (32x64) hi/lo
    {
        const float4* a4 = (const float4*)(A + (size_t)e * 2048);
        const float4* b4 = (const float4*)(B + (size_t)e * 2048);
        #pragma unroll
        for (int rr = 0; rr < 2; rr++) {
            int f = tid + 256 * rr;
            int row = f >> 4, c0 = (f & 15) * 4;
            float4 av = __ldg(&a4[f]);
            float4 bv = __ldg(&b4[f]);
            float aa[4] = {av.x, av.y, av.z, av.w};
            float bb[4] = {bv.x, bv.y, bv.z, bv.w};
            #pragma unroll
            for (int q = 0; q < 4; q++) {
                __nv_bfloat16 h, l;
                split_bf16(aa[q], h, l);
                sA[row][c0 + q] = h; sA[row][68 + c0 + q] = l;
                split_bf16(bb[q], h, l);
                sB[row][c0 + q] = h; sB[row][68 + c0 + q] = l;
            }
        }
    }

    for (int u = 0; u < TPB; u++) {
        int pi = start + u;
        if (pi >= cnt) break;
        int pair = g_list[e * NPAIR + pi];
        int t    = pair >> 1;

        // ---- stage H^T hi/lo ----
        {
            const float4* h4 = (const float4*)&g_h[(size_t)t * 4096];
            #pragma unroll
            for (int rr = 0; rr < 4; rr++) {
                int f = tid + 256 * rr;
                int i = f >> 4, j0 = (f & 15) * 4;
                float4 hv = __ldg(&h4[f]);
                float vv[4] = {hv.x, hv.y, hv.z, hv.w};
                #pragma unroll
                for (int q = 0; q < 4; q++) {
                    __nv_bfloat16 h, l;
                    split_bf16(vv[q], h, l);
                    sHT[j0 + q][i]      = h;
                    sHT[j0 + q][68 + i] = l;
                }
            }
        }
        __syncthreads();

        // ---- T phase: M=32 (mt=warp&1), N=64 (2 n-tiles/warp), 4 k-chunks ----
        {
            const int mt  = warp & 1;
            const int ntb = (warp >> 1) * 2;
            const int R   = mt * 16;
            float d[2][4];
            #pragma unroll
            for (int nn = 0; nn < 2; nn++)
                #pragma unroll
                for (int q = 0; q < 4; q++) d[nn][q] = 0.f;
            #pragma unroll
            for (int kc = 0; kc < 4; kc++) {
                const int ac = kc * 16 + 2 * tig;
                unsigned ah[4], al[4];
                ah[0] = *(const unsigned*)&sA[R + gid][ac];
                ah[1] = *(const unsigned*)&sA[R + gid + 8][ac];
                ah[2] = *(const unsigned*)&sA[R + gid][ac + 8];
                ah[3] = *(const unsigned*)&sA[R + gid + 8][ac + 8];
                al[0] = *(const unsigned*)&sA[R + gid][ac + 68];
                al[1] = *(const unsigned*)&sA[R + gid + 8][ac + 68];
                al[2] = *(const unsigned*)&sA[R + gid][ac + 76];
                al[3] = *(const unsigned*)&sA[R + gid + 8][ac + 76];
                #pragma unroll
                for (int nn = 0; nn < 2; nn++) {
                    const __nv_bfloat16* hr = sHT[(ntb + nn) * 8 + gid];
                    unsigned bh[2], bl[2];
                    bh[0] = *(const unsigned*)&hr[ac];
                    bh[1] = *(const unsigned*)&hr[ac + 8];
                    bl[0] = *(const unsigned*)&hr[ac + 68];
                    bl[1] = *(const unsigned*)&hr[ac + 76];
                    mma_bf16(d[nn], ah, bh);
                    mma_bf16(d[nn], al, bh);
                    mma_bf16(d[nn], ah, bl);
                }
            }
            #pragma unroll
            for (int nn = 0; nn < 2; nn++) {
                int col = (ntb + nn) * 8 + 2 * tig;
                __nv_bfloat16 h0, l0, h1, l1;
                split_bf16(d[nn][0], h0, l0);
                split_bf16(d[nn][1], h1, l1);
                *(__nv_bfloat162*)&sT[R + gid][col]      = __halves2bfloat162(h0, h1);
                *(__nv_bfloat162*)&sT[R + gid][col + 68] = __halves2bfloat162(l0, l1);
                split_bf16(d[nn][2], h0, l0);
                split_bf16(d[nn][3], h1, l1);
                *(__nv_bfloat162*)&sT[R + gid + 8][col]      = __halves2bfloat162(h0, h1);
                *(__nv_bfloat162*)&sT[R + gid + 8][col + 68] = __halves2bfloat162(l0, l1);
            }
        }
        __syncthreads();

        // ---- Y phase: M=32, N=32, 1 tile/warp, 4 k-chunks ----
        {
            const int mt = warp & 1;
            const int nt = warp >> 1;
            const int R  = mt * 16;
            float y[4] = {0.f, 0.f, 0.f, 0.f};
            #pragma unroll
            for (int kc = 0; kc < 4; kc++) {
                const int ac = kc * 16 + 2 * tig;
                unsigned ah[4], al[4];
                ah[0] = *(const unsigned*)&sT[R + gid][ac];
                ah[1] = *(const unsigned*)&sT[R + gid + 8][ac];
                ah[2] = *(const unsigned*)&sT[R + gid][ac + 8];
                ah[3] = *(const unsigned*)&sT[R + gid + 8][ac + 8];
                al[0] = *(const unsigned*)&sT[R + gid][ac + 68];
                al[1] = *(const unsigned*)&sT[R + gid + 8][ac + 68];
                al[2] = *(const unsigned*)&sT[R + gid][ac + 76];
                al[3] = *(const unsigned*)&sT[R + gid + 8][ac + 76];
                const __nv_bfloat16* br = sB[nt * 8 + gid];
                unsigned bh[2], bl[2];
                bh[0] = *(const unsigned*)&br[ac];
                bh[1] = *(const unsigned*)&br[ac + 8];
                bl[0] = *(const unsigned*)&br[ac + 68];
                bl[1] = *(const unsigned*)&br[ac + 76];
                mma_bf16(y, ah, bh);
                mma_bf16(y, al, bh);
                mma_bf16(y, ah, bl);
            }
            float* yo = &g_ydown[(size_t)pair * 1024];
            int col = nt * 8 + 2 * tig;
            *(float2*)&yo[(R + gid) * 32 + col]     = make_float2(y[0], y[1]);
            *(float2*)&yo[(R + gid + 8) * 32 + col] = make_float2(y[2], y[3]);
        }
        __syncthreads();
    }
}

// ---------------------------------------------------------------------------
// Final combine (down)
// ---------------------------------------------------------------------------
__global__ __launch_bounds__(256) void combine_down(
    const float* __restrict__ scale, const float* __restrict__ bias,
    float* __restrict__ out)
{
    const int t   = blockIdx.x;
    const int tid = threadIdx.x;
    const float p0 = g_prob[2 * t], p1 = g_prob[2 * t + 1];
    const float s  = __ldg(scale);
    const float4* y0 = (const float4*)&g_ydown[(size_t)(2 * t) * 1024];
    const float4* y1 = (const float4*)&g_ydown[(size_t)(2 * t + 1) * 1024];
    const float4* b4 = (const float4*)bias;
    float4 a = __ldg(&y0[tid]), c = __ldg(&y1[tid]), bb = __ldg(&b4[tid]);
    float4 v;
    v.x = s * (p0 * a.x + p1 * c.x) + bb.x;
    v.y = s * (p0 * a.y + p1 * c.y) + bb.y;
    v.z = s * (p0 * a.z + p1 * c.z) + bb.z;
    v.w = s * (p0 * a.w + p1 * c.w) + bb.w;
    ((float4*)&out[(size_t)t * 1024])[tid] = v;
}

// ---------------------------------------------------------------------------
extern "C" void kernel_launch(void* const* d_in, const int* in_sizes, int n_in,
                              void* d_out, int out_size)
{
    const float* x          = (const float*)d_in[0];
    const float* W_up       = (const float*)d_in[1];
    const float* A_up       = (const float*)d_in[2];
    const float* B_up       = (const float*)d_in[3];
    const float* scale_up   = (const float*)d_in[4];
    const float* bias_up    = (const float*)d_in[5];
    const float* W_down     = (const float*)d_in[6];
    const float* A_down     = (const float*)d_in[7];
    const float* B_down     = (const float*)d_in[8];
    const float* scale_down = (const float*)d_in[9];
    const float* bias_down  = (const float*)d_in[10];
    float*       out        = (float*)d_out;

    const int n_tok = in_sizes[0] / 1024;     // 8192

    float *lg1 = nullptr, *lg2 = nullptr;
    cudaGetSymbolAddress((void**)&lg1, g_logits);
    cudaGetSymbolAddress((void**)&lg2, g_logits2);

    // ---- up ----
    router_up<<<n_tok / 64, 256>>>(x, W_up, lg1);
    top2_kernel<<<n_tok / 8, 256>>>(lg1, nullptr);
    prefix_kernel<<<1, 64>>>();
    bilinear_up<<<MAXCHUNK, 256>>>(x, A_up, B_up);

    // ---- down (combine_up fused into router staging; K split x2) ----
    router_down_fused<<<2 * (n_tok / 64), 256>>>(W_down, scale_up, bias_up, lg1, lg2);
    top2_kernel<<<n_tok / 8, 256>>>(lg1, lg2);
    prefix_kernel<<<1, 64>>>();
    bilinear_down<<<MAXCHUNK, 256>>>(A_down, B_down);
    combine_down<<<n_tok, 256>>>(scale_down, bias_down, out);
}

// round 15
// speedup vs baseline: 1.0658x; 1.0658x over previous
#include <cuda_runtime.h>
#include <cuda_bf16.h>
#include <math.h>

#define NTOK   8192
#define NPAIR  (NTOK * 2)
#define NE     64
#define TPB    16
#define MAXCHUNK (NPAIR / TPB + NE)   // 1088

// ---- scratch (device globals; no allocs allowed) ----
__device__ float g_h[(size_t)NTOK * 4096];        // 134 MB
__device__ float g_yup[(size_t)NPAIR * 4096];     // 268 MB
__device__ float g_ydown[(size_t)NPAIR * 1024];   // 67 MB
__device__ float g_logits[(size_t)NTOK * NE];     // 2 MB
__device__ float g_logits2[(size_t)NTOK * NE];    // 2 MB (K-split partial)
__device__ float g_prob[NPAIR];
__device__ int   g_cnt[NE];
__device__ int   g_list[NE * NPAIR];              // 4 MB
__device__ int2  g_chunk[MAXCHUNK];
__device__ int   g_nchunks;

__device__ __forceinline__ float gelu_erf(float v) { return v * normcdff(v); }

// split fp32 into bf16 hi + bf16 lo (v ~= hi + lo, |resid| <~ 2^-18 |v|)
__device__ __forceinline__ void split_bf16(float v, __nv_bfloat16& h, __nv_bfloat16& l) {
    h = __float2bfloat16_rn(v);
    l = __float2bfloat16_rn(v - __bfloat162float(h));
}

// one m16n8k16 bf16 mma, fp32 accumulate (in place)
__device__ __forceinline__ void mma_bf16(float* d, const unsigned* a, const unsigned* b) {
    asm volatile(
        "mma.sync.aligned.m16n8k16.row.col.f32.bf16.bf16.f32 "
        "{%0,%1,%2,%3}, {%4,%5,%6,%7}, {%8,%9}, {%0,%1,%2,%3};"
        : "+f"(d[0]), "+f"(d[1]), "+f"(d[2]), "+f"(d[3])
        : "r"(a[0]), "r"(a[1]), "r"(a[2]), "r"(a[3]), "r"(b[0]), "r"(b[1]));
}

// named barrier: 128-thread group sync (ids 1,2)
__device__ __forceinline__ void bar_group(int id) {
    asm volatile("bar.sync %0, 128;" :: "r"(id) : "memory");
}

// ---------------------------------------------------------------------------
// Router GEMM (fp32-exact SIMT): logits = X W^T, 64-token tiles.
// NPARTS=2: grid doubles; upper half computes k in [KLEN,2*KLEN) -> out1.
// ---------------------------------------------------------------------------
template<int KLEN, int NPARTS>
__global__ __launch_bounds__(256) void router_gemm(
    const float* __restrict__ X, const float* __restrict__ W,
    float* __restrict__ out0, float* __restrict__ out1, int ld)
{
    __shared__ __align__(16) float sX[64][33];    // [m][k] scalar distinct reads
    __shared__ __align__(16) float sWT[32][68];   // [k][e] uniform float4 reads
    const int tid  = threadIdx.x;
    const int lane = tid & 31;
    const int warp = tid >> 5;
    if (blockIdx.x == 0 && tid < NE) g_cnt[tid] = 0;   // reset for top2

    const int part  = (NPARTS == 2) ? (blockIdx.x >> 7) : 0;
    const int bx    = (NPARTS == 2) ? (blockIdx.x & 127) : blockIdx.x;
    const int k_off = part * KLEN;
    float* outp     = part ? out1 : out0;

    const int m0 = bx * 64;
    const int eb = warp * 8;

    float acc[2][8];
    #pragma unroll
    for (int i = 0; i < 2; i++)
        #pragma unroll
        for (int j = 0; j < 8; j++) acc[i][j] = 0.f;

    for (int kc = 0; kc < KLEN; kc += 32) {
        #pragma unroll
        for (int rr = 0; rr < 2; rr++) {
            int f = tid + 256 * rr;
            int m = f >> 3, kl = (f & 7) * 4;
            float4 v = __ldg((const float4*)&X[(size_t)(m0 + m) * ld + k_off + kc + kl]);
            sX[m][kl] = v.x; sX[m][kl+1] = v.y; sX[m][kl+2] = v.z; sX[m][kl+3] = v.w;
        }
        #pragma unroll
        for (int rr = 0; rr < 2; rr++) {
            int f = tid + 256 * rr;
            int e = f >> 3, kl = (f & 7) * 4;
            float4 v = __ldg((const float4*)&W[(size_t)e * ld + k_off + kc + kl]);
            sWT[kl][e] = v.x; sWT[kl+1][e] = v.y; sWT[kl+2][e] = v.z; sWT[kl+3][e] = v.w;
        }
        __syncthreads();
        #pragma unroll
        for (int k = 0; k < 32; k++) {
            float x0 = sX[lane][k];
            float x1 = sX[lane + 32][k];
            float4 wa = *(const float4*)&sWT[k][eb];
            float4 wb = *(const float4*)&sWT[k][eb + 4];
            acc[0][0] += x0*wa.x; acc[0][1] += x0*wa.y; acc[0][2] += x0*wa.z; acc[0][3] += x0*wa.w;
            acc[0][4] += x0*wb.x; acc[0][5] += x0*wb.y; acc[0][6] += x0*wb.z; acc[0][7] += x0*wb.w;
            acc[1][0] += x1*wa.x; acc[1][1] += x1*wa.y; acc[1][2] += x1*wa.z; acc[1][3] += x1*wa.w;
            acc[1][4] += x1*wb.x; acc[1][5] += x1*wb.y; acc[1][6] += x1*wb.z; acc[1][7] += x1*wb.w;
        }
        __syncthreads();
    }
    #pragma unroll
    for (int mm = 0; mm < 2; mm++) {
        float* lg = &outp[(size_t)(m0 + lane + 32 * mm) * NE + eb];
        *(float4*)lg       = make_float4(acc[mm][0], acc[mm][1], acc[mm][2], acc[mm][3]);
        *(float4*)(lg + 4) = make_float4(acc[mm][4], acc[mm][5], acc[mm][6], acc[mm][7]);
    }
}

// ---------------------------------------------------------------------------
// Top-2 + softmax + per-expert list build.
// ---------------------------------------------------------------------------
__global__ __launch_bounds__(256) void top2_kernel(
    const float* __restrict__ lg1, const float* __restrict__ lg2)
{
    const int t    = blockIdx.x * 8 + (threadIdx.x >> 5);
    const int lane = threadIdx.x & 31;
    float v0 = lg1[(size_t)t * NE + lane];
    float v1 = lg1[(size_t)t * NE + lane + 32];
    if (lg2) {
        v0 += lg2[(size_t)t * NE + lane];
        v1 += lg2[(size_t)t * NE + lane + 32];
    }

    float m1; int i1;
    if (v0 >= v1) { m1 = v0; i1 = lane; } else { m1 = v1; i1 = lane + 32; }
    #pragma unroll
    for (int off = 16; off > 0; off >>= 1) {
        float om = __shfl_xor_sync(0xffffffffu, m1, off);
        int   oi = __shfl_xor_sync(0xffffffffu, i1, off);
        if (om > m1 || (om == m1 && oi < i1)) { m1 = om; i1 = oi; }
    }
    float c0 = (lane == i1)      ? -INFINITY : v0;
    float c1 = (lane + 32 == i1) ? -INFINITY : v1;
    float m2; int i2;
    if (c0 >= c1) { m2 = c0; i2 = lane; } else { m2 = c1; i2 = lane + 32; }
    #pragma unroll
    for (int off = 16; off > 0; off >>= 1) {
        float om = __shfl_xor_sync(0xffffffffu, m2, off);
        int   oi = __shfl_xor_sync(0xffffffffu, i2, off);
        if (om > m2 || (om == m2 && oi < i2)) { m2 = om; i2 = oi; }
    }
    if (lane == 0) {
        float p1 = 1.f / (1.f + expf(m2 - m1));
        g_prob[2 * t]     = p1;
        g_prob[2 * t + 1] = 1.f - p1;
        int pos = atomicAdd(&g_cnt[i1], 1);
        g_list[i1 * NPAIR + pos] = 2 * t;
        pos = atomicAdd(&g_cnt[i2], 1);
        g_list[i2 * NPAIR + pos] = 2 * t + 1;
    }
}

__global__ void prefix_kernel()
{
    __shared__ int s_c[NE];
    __shared__ int s_off[NE];
    const int e = threadIdx.x;
    int c = (g_cnt[e] + TPB - 1) / TPB;
    s_c[e] = c;
    __syncthreads();
    if (e == 0) {
        int s = 0;
        for (int i = 0; i < NE; i++) { s_off[i] = s; s += s_c[i]; }
        g_nchunks = s;
    }
    __syncthreads();
    int o = s_off[e];
    for (int i = 0; i < c; i++)
        g_chunk[o + i] = make_int2(e, i * TPB);
}

// ---------------------------------------------------------------------------
// Up bilinear, bf16 3-product, DUAL-PIPELINE:
// two independent 128-thread groups (pl = warp>>2), each owning one pair
// per iteration, synced only by named barriers (bar.sync 1+pl, 128).
// sA/sB are read-only after the single block-wide sync.
// ---------------------------------------------------------------------------
__global__ __launch_bounds__(256) void bilinear_up(
    const float* __restrict__ x, const float* __restrict__ A, const float* __restrict__ B)
{
    const int b = blockIdx.x;
    if (b >= g_nchunks) return;
    const int2 ch   = g_chunk[b];
    const int e     = ch.x;
    const int start = ch.y;
    const int cnt   = g_cnt[e];
    const int tid   = threadIdx.x;
    const int lane  = tid & 31;
    const int warp  = tid >> 5;
    const int gid   = lane >> 2;    // 0..7
    const int tig   = lane & 3;     // 0..3

    __shared__ __align__(16) __nv_bfloat16 sA[64][72];     // A-op: [o][ihi 0-31 | ilo 36-67]
    __shared__ __align__(16) __nv_bfloat16 sB[64][72];     // B-op: [p][jhi | jlo]
    __shared__ __align__(16) __nv_bfloat16 sXT[2][32][72]; // B-op: [j][ihi | ilo]  (X^T)
    __shared__ __align__(16) __nv_bfloat16 sT[2][64][72];  // A-op: [o][jhi | jlo]

    // stage A_up[e] (64x32) and B_up[e] (64x32) hi/lo  (block-wide, once)
    {
        const float4* a4 = (const float4*)(A + (size_t)e * 2048);
        const float4* b4 = (const float4*)(B + (size_t)e * 2048);
        #pragma unroll
        for (int rr = 0; rr < 2; rr++) {
            int f = tid + 256 * rr;
            int row = f >> 3, c0 = (f & 7) * 4;
            float4 av = __ldg(&a4[f]);
            float4 bv = __ldg(&b4[f]);
            float aa[4] = {av.x, av.y, av.z, av.w};
            float bb[4] = {bv.x, bv.y, bv.z, bv.w};
            #pragma unroll
            for (int q = 0; q < 4; q++) {
                __nv_bfloat16 h, l;
                split_bf16(aa[q], h, l);
                sA[row][c0 + q] = h; sA[row][36 + c0 + q] = l;
                split_bf16(bb[q], h, l);
                sB[row][c0 + q] = h; sB[row][36 + c0 + q] = l;
            }
        }
    }
    __syncthreads();   // the ONLY block-wide sync

    const int pl     = warp >> 2;      // pipeline/group 0 or 1
    const int bar    = pl + 1;         // named barrier id
    const int tid128 = tid & 127;
    const int mt     = warp & 3;       // m-tile within group
    const int R      = mt * 16;

    // group pl processes pairs start+pl, start+pl+2, ...
    for (int u = pl; u < TPB; u += 2) {
        int pi = start + u;
        if (pi >= cnt) break;                  // group-uniform
        int pair = g_list[e * NPAIR + pi];
        int t    = pair >> 1;

        // ---- stage this group's X^T hi/lo (128 threads, 2 float4 each) ----
        #pragma unroll
        for (int rr = 0; rr < 2; rr++) {
            int f = tid128 + 128 * rr;
            int i = f >> 3, j0 = (f & 7) * 4;
            float4 xv = __ldg((const float4*)&x[(size_t)t * 1024 + f * 4]);
            float vv[4] = {xv.x, xv.y, xv.z, xv.w};
            #pragma unroll
            for (int q = 0; q < 4; q++) {
                __nv_bfloat16 h, l;
                split_bf16(vv[q], h, l);
                sXT[pl][j0 + q][i]      = h;
                sXT[pl][j0 + q][36 + i] = l;
            }
        }
        bar_group(bar);

        // ---- T phase: D[64,32], 2 k-chunks x 3 products ----
        {
            float d[4][4];
            #pragma unroll
            for (int nt = 0; nt < 4; nt++)
                #pragma unroll
                for (int q = 0; q < 4; q++) d[nt][q] = 0.f;
            #pragma unroll
            for (int kc = 0; kc < 2; kc++) {
                const int ac = kc * 16 + 2 * tig;
                unsigned ah[4], al[4];
                ah[0] = *(const unsigned*)&sA[R + gid][ac];
                ah[1] = *(const unsigned*)&sA[R + gid + 8][ac];
                ah[2] = *(const unsigned*)&sA[R + gid][ac + 8];
                ah[3] = *(const unsigned*)&sA[R + gid + 8][ac + 8];
                al[0] = *(const unsigned*)&sA[R + gid][ac + 36];
                al[1] = *(const unsigned*)&sA[R + gid + 8][ac + 36];
                al[2] = *(const unsigned*)&sA[R + gid][ac + 44];
                al[3] = *(const unsigned*)&sA[R + gid + 8][ac + 44];
                #pragma unroll
                for (int nt = 0; nt < 4; nt++) {
                    const __nv_bfloat16* xr = sXT[pl][nt * 8 + gid];
                    unsigned bh[2], bl[2];
                    bh[0] = *(const unsigned*)&xr[ac];
                    bh[1] = *(const unsigned*)&xr[ac + 8];
                    bl[0] = *(const unsigned*)&xr[ac + 36];
                    bl[1] = *(const unsigned*)&xr[ac + 44];
                    mma_bf16(d[nt], ah, bh);
                    mma_bf16(d[nt], al, bh);
                    mma_bf16(d[nt], ah, bl);
                }
            }
            // store T hi/lo
            #pragma unroll
            for (int nt = 0; nt < 4; nt++) {
                int col = nt * 8 + 2 * tig;
                __nv_bfloat16 h0, l0, h1, l1;
                split_bf16(d[nt][0], h0, l0);
                split_bf16(d[nt][1], h1, l1);
                *(__nv_bfloat162*)&sT[pl][R + gid][col]      = __halves2bfloat162(h0, h1);
                *(__nv_bfloat162*)&sT[pl][R + gid][col + 36] = __halves2bfloat162(l0, l1);
                split_bf16(d[nt][2], h0, l0);
                split_bf16(d[nt][3], h1, l1);
                *(__nv_bfloat162*)&sT[pl][R + gid + 8][col]      = __halves2bfloat162(h0, h1);
                *(__nv_bfloat162*)&sT[pl][R + gid + 8][col + 36] = __halves2bfloat162(l0, l1);
            }
        }
        bar_group(bar);

        // ---- Y phase: D[64,64], 2 k-chunks x 3 products ----
        {
            float y[8][4];
            #pragma unroll
            for (int nt = 0; nt < 8; nt++)
                #pragma unroll
                for (int q = 0; q < 4; q++) y[nt][q] = 0.f;
            #pragma unroll
            for (int kc = 0; kc < 2; kc++) {
                const int ac = kc * 16 + 2 * tig;
                unsigned ah[4], al[4];
                ah[0] = *(const unsigned*)&sT[pl][R + gid][ac];
                ah[1] = *(const unsigned*)&sT[pl][R + gid + 8][ac];
                ah[2] = *(const unsigned*)&sT[pl][R + gid][ac + 8];
                ah[3] = *(const unsigned*)&sT[pl][R + gid + 8][ac + 8];
                al[0] = *(const unsigned*)&sT[pl][R + gid][ac + 36];
                al[1] = *(const unsigned*)&sT[pl][R + gid + 8][ac + 36];
                al[2] = *(const unsigned*)&sT[pl][R + gid][ac + 44];
                al[3] = *(const unsigned*)&sT[pl][R + gid + 8][ac + 44];
                #pragma unroll
                for (int nt = 0; nt < 8; nt++) {
                    const __nv_bfloat16* br = sB[nt * 8 + gid];
                    unsigned bh[2], bl[2];
                    bh[0] = *(const unsigned*)&br[ac];
                    bh[1] = *(const unsigned*)&br[ac + 8];
                    bl[0] = *(const unsigned*)&br[ac + 36];
                    bl[1] = *(const unsigned*)&br[ac + 44];
                    mma_bf16(y[nt], ah, bh);
                    mma_bf16(y[nt], al, bh);
                    mma_bf16(y[nt], ah, bl);
                }
            }
            float* yo = &g_yup[(size_t)pair * 4096];
            #pragma unroll
            for (int nt = 0; nt < 8; nt++) {
                int col = nt * 8 + 2 * tig;
                *(float2*)&yo[(R + gid) * 64 + col]     = make_float2(y[nt][0], y[nt][1]);
                *(float2*)&yo[(R + gid + 8) * 64 + col] = make_float2(y[nt][2], y[nt][3]);
            }
        }
        bar_group(bar);   // protect sXT/sT before next iteration's staging
    }
}

// ---------------------------------------------------------------------------
// Down bilinear, bf16 3-product (R10, passing).
// ---------------------------------------------------------------------------
__global__ __launch_bounds__(256) void bilinear_down(
    const float* __restrict__ A, const float* __restrict__ B)
{
    const int b = blockIdx.x;
    if (b >= g_nchunks) return;
    const int2 ch   = g_chunk[b];
    const int e     = ch.x;
    const int start = ch.y;
    const int cnt   = g_cnt[e];
    const int tid   = threadIdx.x;
    const int lane  = tid & 31;
    const int warp  = tid >> 5;
    const int gid   = lane >> 2;
    const int tig   = lane & 3;

    __shared__ __align__(16) __nv_bfloat16 sA[32][136];   // A-op: [o][ihi 0-63 | ilo 68-131]
    __shared__ __align__(16) __nv_bfloat16 sB[32][136];   // B-op: [p][jhi | jlo]
    __shared__ __align__(16) __nv_bfloat16 sHT[64][136];  // B-op: [j][ihi | ilo]  (H^T)
    __shared__ __align__(16) __nv_bfloat16 sT[32][136];   // A-op: [o][jhi | jlo]

    // stage A_down[e] (32x64), B_down[e] (32x64) hi/lo
    {
        const float4* a4 = (const float4*)(A + (size_t)e * 2048);
        const float4* b4 = (const float4*)(B + (size_t)e * 2048);
        #pragma unroll
        for (int rr = 0; rr < 2; rr++) {
            int f = tid + 256 * rr;
            int row = f >> 4, c0 = (f & 15) * 4;
            float4 av = __ldg(&a4[f]);
            float4 bv = __ldg(&b4[f]);
            float aa[4] = {av.x, av.y, av.z, av.w};
            float bb[4] = {bv.x, bv.y, bv.z, bv.w};
            #pragma unroll
            for (int q = 0; q < 4; q++) {
                __nv_bfloat16 h, l;
                split_bf16(aa[q], h, l);
                sA[row][c0 + q] = h; sA[row][68 + c0 + q] = l;
                split_bf16(bb[q], h, l);
                sB[row][c0 + q] = h; sB[row][68 + c0 + q] = l;
            }
        }
    }

    for (int u = 0; u < TPB; u++) {
        int pi = start + u;
        if (pi >= cnt) break;
        int pair = g_list[e * NPAIR + pi];
        int t    = pair >> 1;

        // ---- stage H^T hi/lo ----
        {
            const float4* h4 = (const float4*)&g_h[(size_t)t * 4096];
            #pragma unroll
            for (int rr = 0; rr < 4; rr++) {
                int f = tid + 256 * rr;
                int i = f >> 4, j0 = (f & 15) * 4;
                float4 hv = __ldg(&h4[f]);
                float vv[4] = {hv.x, hv.y, hv.z, hv.w};
                #pragma unroll
                for (int q = 0; q < 4; q++) {
                    __nv_bfloat16 h, l;
                    split_bf16(vv[q], h, l);
                    sHT[j0 + q][i]      = h;
                    sHT[j0 + q][68 + i] = l;
                }
            }
        }
        __syncthreads();

        // ---- T phase: M=32 (mt=warp&1), N=64 (2 n-tiles/warp), 4 k-chunks ----
        {
            const int mt  = warp & 1;
            const int ntb = (warp >> 1) * 2;
            const int R   = mt * 16;
            float d[2][4];
            #pragma unroll
            for (int nn = 0; nn < 2; nn++)
                #pragma unroll
                for (int q = 0; q < 4; q++) d[nn][q] = 0.f;
            #pragma unroll
            for (int kc = 0; kc < 4; kc++) {
                const int ac = kc * 16 + 2 * tig;
                unsigned ah[4], al[4];
                ah[0] = *(const unsigned*)&sA[R + gid][ac];
                ah[1] = *(const unsigned*)&sA[R + gid + 8][ac];
                ah[2] = *(const unsigned*)&sA[R + gid][ac + 8];
                ah[3] = *(const unsigned*)&sA[R + gid + 8][ac + 8];
                al[0] = *(const unsigned*)&sA[R + gid][ac + 68];
                al[1] = *(const unsigned*)&sA[R + gid + 8][ac + 68];
                al[2] = *(const unsigned*)&sA[R + gid][ac + 76];
                al[3] = *(const unsigned*)&sA[R + gid + 8][ac + 76];
                #pragma unroll
                for (int nn = 0; nn < 2; nn++) {
                    const __nv_bfloat16* hr = sHT[(ntb + nn) * 8 + gid];
                    unsigned bh[2], bl[2];
                    bh[0] = *(const unsigned*)&hr[ac];
                    bh[1] = *(const unsigned*)&hr[ac + 8];
                    bl[0] = *(const unsigned*)&hr[ac + 68];
                    bl[1] = *(const unsigned*)&hr[ac + 76];
                    mma_bf16(d[nn], ah, bh);
                    mma_bf16(d[nn], al, bh);
                    mma_bf16(d[nn], ah, bl);
                }
            }
            #pragma unroll
            for (int nn = 0; nn < 2; nn++) {
                int col = (ntb + nn) * 8 + 2 * tig;
                __nv_bfloat16 h0, l0, h1, l1;
                split_bf16(d[nn][0], h0, l0);
                split_bf16(d[nn][1], h1, l1);
                *(__nv_bfloat162*)&sT[R + gid][col]      = __halves2bfloat162(h0, h1);
                *(__nv_bfloat162*)&sT[R + gid][col + 68] = __halves2bfloat162(l0, l1);
                split_bf16(d[nn][2], h0, l0);
                split_bf16(d[nn][3], h1, l1);
                *(__nv_bfloat162*)&sT[R + gid + 8][col]      = __halves2bfloat162(h0, h1);
                *(__nv_bfloat162*)&sT[R + gid + 8][col + 68] = __halves2bfloat162(l0, l1);
            }
        }
        __syncthreads();

        // ---- Y phase: M=32, N=32, 1 tile/warp, 4 k-chunks ----
        {
            const int mt = warp & 1;
            const int nt = warp >> 1;
            const int R  = mt * 16;
            float y[4] = {0.f, 0.f, 0.f, 0.f};
            #pragma unroll
            for (int kc = 0; kc < 4; kc++) {
                const int ac = kc * 16 + 2 * tig;
                unsigned ah[4], al[4];
                ah[0] = *(const unsigned*)&sT[R + gid][ac];
                ah[1] = *(const unsigned*)&sT[R + gid + 8][ac];
                ah[2] = *(const unsigned*)&sT[R + gid][ac + 8];
                ah[3] = *(const unsigned*)&sT[R + gid + 8][ac + 8];
                al[0] = *(const unsigned*)&sT[R + gid][ac + 68];
                al[1] = *(const unsigned*)&sT[R + gid + 8][ac + 68];
                al[2] = *(const unsigned*)&sT[R + gid][ac + 76];
                al[3] = *(const unsigned*)&sT[R + gid + 8][ac + 76];
                const __nv_bfloat16* br = sB[nt * 8 + gid];
                unsigned bh[2], bl[2];
                bh[0] = *(const unsigned*)&br[ac];
                bh[1] = *(const unsigned*)&br[ac + 8];
                bl[0] = *(const unsigned*)&br[ac + 68];
                bl[1] = *(const unsigned*)&br[ac + 76];
                mma_bf16(y, ah, bh);
                mma_bf16(y, al, bh);
                mma_bf16(y, ah, bl);
            }
            float* yo = &g_ydown[(size_t)pair * 1024];
            int col = nt * 8 + 2 * tig;
            *(float2*)&yo[(R + gid) * 32 + col]     = make_float2(y[0], y[1]);
            *(float2*)&yo[(R + gid + 8) * 32 + col] = make_float2(y[2], y[3]);
        }
        __syncthreads();
    }
}

// ---------------------------------------------------------------------------
// Combine kernels (R10, passing)
// ---------------------------------------------------------------------------
__global__ __launch_bounds__(256) void combine_up(
    const float* __restrict__ scale, const float* __restrict__ bias)
{
    const int t   = blockIdx.x;
    const int tid = threadIdx.x;
    const float p0 = g_prob[2 * t], p1 = g_prob[2 * t + 1];
    const float s  = __ldg(scale);
    const float4* y0 = (const float4*)&g_yup[(size_t)(2 * t) * 4096];
    const float4* y1 = (const float4*)&g_yup[(size_t)(2 * t + 1) * 4096];
    const float4* b4 = (const float4*)bias;
    float4* h4 = (float4*)&g_h[(size_t)t * 4096];
    #pragma unroll
    for (int rr = 0; rr < 4; rr++) {
        int f = tid + 256 * rr;
        float4 a = __ldg(&y0[f]), c = __ldg(&y1[f]), bb = __ldg(&b4[f]);
        float4 v;
        v.x = gelu_erf(s * (p0 * a.x + p1 * c.x) + bb.x);
        v.y = gelu_erf(s * (p0 * a.y + p1 * c.y) + bb.y);
        v.z = gelu_erf(s * (p0 * a.z + p1 * c.z) + bb.z);
        v.w = gelu_erf(s * (p0 * a.w + p1 * c.w) + bb.w);
        h4[f] = v;
    }
}

__global__ __launch_bounds__(256) void combine_down(
    const float* __restrict__ scale, const float* __restrict__ bias,
    float* __restrict__ out)
{
    const int t   = blockIdx.x;
    const int tid = threadIdx.x;
    const float p0 = g_prob[2 * t], p1 = g_prob[2 * t + 1];
    const float s  = __ldg(scale);
    const float4* y0 = (const float4*)&g_ydown[(size_t)(2 * t) * 1024];
    const float4* y1 = (const float4*)&g_ydown[(size_t)(2 * t + 1) * 1024];
    const float4* b4 = (const float4*)bias;
    float4 a = __ldg(&y0[tid]), c = __ldg(&y1[tid]), bb = __ldg(&b4[tid]);
    float4 v;
    v.x = s * (p0 * a.x + p1 * c.x) + bb.x;
    v.y = s * (p0 * a.y + p1 * c.y) + bb.y;
    v.z = s * (p0 * a.z + p1 * c.z) + bb.z;
    v.w = s * (p0 * a.w + p1 * c.w) + bb.w;
    ((float4*)&out[(size_t)t * 1024])[tid] = v;
}

// ---------------------------------------------------------------------------
extern "C" void kernel_launch(void* const* d_in, const int* in_sizes, int n_in,
                              void* d_out, int out_size)
{
    const float* x          = (const float*)d_in[0];
    const float* W_up       = (const float*)d_in[1];
    const float* A_up       = (const float*)d_in[2];
    const float* B_up       = (const float*)d_in[3];
    const float* scale_up   = (const float*)d_in[4];
    const float* bias_up    = (const float*)d_in[5];
    const float* W_down     = (const float*)d_in[6];
    const float* A_down     = (const float*)d_in[7];
    const float* B_down     = (const float*)d_in[8];
    const float* scale_down = (const float*)d_in[9];
    const float* bias_down  = (const float*)d_in[10];
    float*       out        = (float*)d_out;

    const int n_tok = in_sizes[0] / 1024;     // 8192

    float *h_ptr = nullptr, *lg1 = nullptr, *lg2 = nullptr;
    cudaGetSymbolAddress((void**)&h_ptr, g_h);
    cudaGetSymbolAddress((void**)&lg1, g_logits);
    cudaGetSymbolAddress((void**)&lg2, g_logits2);

    // ---- up ----
    router_gemm<1024, 1><<<n_tok / 64, 256>>>(x, W_up, lg1, nullptr, 1024);
    top2_kernel<<<n_tok / 8, 256>>>(lg1, nullptr);
    prefix_kernel<<<1, 64>>>();
    bilinear_up<<<MAXCHUNK, 256>>>(x, A_up, B_up);
    combine_up<<<n_tok, 256>>>(scale_up, bias_up);

    // ---- down (K split in 2 within one 256-block launch) ----
    router_gemm<2048, 2><<<2 * (n_tok / 64), 256>>>(h_ptr, W_down, lg1, lg2, 4096);
    top2_kernel<<<n_tok / 8, 256>>>(lg1, lg2);
    prefix_kernel<<<1, 64>>>();
    bilinear_down<<<MAXCHUNK, 256>>>(A_down, B_down);
    combine_down<<<n_tok, 256>>>(scale_down, bias_down, out);
}

// round 16
// speedup vs baseline: 1.1522x; 1.0810x over previous
#include <cuda_runtime.h>
#include <cuda_bf16.h>
#include <cuda_fp16.h>
#include <math.h>

#define NTOK   8192
#define NPAIR  (NTOK * 2)
#define NE     64
#define TPB    16
#define MAXCHUNK (NPAIR / TPB + NE)   // 1088

// ---- scratch (device globals; no allocs allowed) ----
__device__ float g_h[(size_t)NTOK * 4096];        // 134 MB
__device__ float g_yup[(size_t)NPAIR * 4096];     // 268 MB
__device__ float g_ydown[(size_t)NPAIR * 1024];   // 67 MB
__device__ float g_logits[(size_t)NTOK * NE];     // 2 MB
__device__ float g_logits2[(size_t)NTOK * NE];    // 2 MB (K-split partial)
__device__ float g_prob[NPAIR];
__device__ int   g_cnt[NE];
__device__ int   g_list[NE * NPAIR];              // 4 MB
__device__ int2  g_chunk[MAXCHUNK];
__device__ int   g_nchunks;

__device__ __forceinline__ float gelu_erf(float v) { return v * normcdff(v); }

// split fp32 into bf16 hi + bf16 lo (v ~= hi + lo, |resid| <~ 2^-18 |v|)
__device__ __forceinline__ void split_bf16(float v, __nv_bfloat16& h, __nv_bfloat16& l) {
    h = __float2bfloat16_rn(v);
    l = __float2bfloat16_rn(v - __bfloat162float(h));
}

// split fp32 into fp16 hi + SCALED fp16 lo: v ~= hi + lo*2^-11.
// Scaling keeps lo in fp16 normal range (no subnormal precision loss).
__device__ __forceinline__ void split_f16s(float v, __half& h, __half& l) {
    h = __float2half_rn(v);
    l = __float2half_rn((v - __half2float(h)) * 2048.0f);
}

// one m16n8k16 bf16 mma, fp32 accumulate (in place)
__device__ __forceinline__ void mma_bf16(float* d, const unsigned* a, const unsigned* b) {
    asm volatile(
        "mma.sync.aligned.m16n8k16.row.col.f32.bf16.bf16.f32 "
        "{%0,%1,%2,%3}, {%4,%5,%6,%7}, {%8,%9}, {%0,%1,%2,%3};"
        : "+f"(d[0]), "+f"(d[1]), "+f"(d[2]), "+f"(d[3])
        : "r"(a[0]), "r"(a[1]), "r"(a[2]), "r"(a[3]), "r"(b[0]), "r"(b[1]));
}

// one m16n8k16 fp16 mma, fp32 accumulate (in place)
__device__ __forceinline__ void mma_f16(float* d, const unsigned* a, const unsigned* b) {
    asm volatile(
        "mma.sync.aligned.m16n8k16.row.col.f32.f16.f16.f32 "
        "{%0,%1,%2,%3}, {%4,%5,%6,%7}, {%8,%9}, {%0,%1,%2,%3};"
        : "+f"(d[0]), "+f"(d[1]), "+f"(d[2]), "+f"(d[3])
        : "r"(a[0]), "r"(a[1]), "r"(a[2]), "r"(a[3]), "r"(b[0]), "r"(b[1]));
}

// named barrier: 128-thread group sync (ids 1,2)
__device__ __forceinline__ void bar_group(int id) {
    asm volatile("bar.sync %0, 128;" :: "r"(id) : "memory");
}

// ---------------------------------------------------------------------------
// Router GEMM, fp16 3-product with scaled-lo (near-fp32, ~3e-7 abs logit err):
// logits[64tok, 64exp] = X W^T per tile. A = X rows [m][k]; B = W rows [e][k]
// (native K-major, "col" operand). 8 warps: mt = warp&3 (16 rows),
// nh = warp>>2 (32 cols = 4 n-tiles). acc0 = hh products; acc1 = cross
// products at 2^11 scale; d = acc0 + acc1 * 2^-11 (exact fold).
// NPARTS=2: grid doubles; upper half -> out1 (K-split, summed in top2).
// ---------------------------------------------------------------------------
template<int KLEN, int NPARTS>
__global__ __launch_bounds__(256) void router_f16(
    const float* __restrict__ X, const float* __restrict__ W,
    float* __restrict__ out0, float* __restrict__ out1, int ld)
{
    __shared__ __align__(16) __half sX[64][72];   // [m][khi 0-31 | klo 36-67]
    __shared__ __align__(16) __half sW[64][72];   // [e][khi | klo]
    const int tid  = threadIdx.x;
    const int lane = tid & 31;
    const int warp = tid >> 5;
    const int gid  = lane >> 2;
    const int tig  = lane & 3;
    if (blockIdx.x == 0 && tid < NE) g_cnt[tid] = 0;   // reset for top2

    const int part  = (NPARTS == 2) ? (blockIdx.x >> 7) : 0;
    const int bx    = (NPARTS == 2) ? (blockIdx.x & 127) : blockIdx.x;
    const int k_off = part * KLEN;
    float* outp     = part ? out1 : out0;

    const int m0 = bx * 64;
    const int mt = warp & 3;
    const int R  = mt * 16;
    const int nh = warp >> 2;          // 0/1 -> cols nh*32 .. nh*32+31

    float acc0[4][4], acc1[4][4];
    #pragma unroll
    for (int nt = 0; nt < 4; nt++)
        #pragma unroll
        for (int q = 0; q < 4; q++) { acc0[nt][q] = 0.f; acc1[nt][q] = 0.f; }

    for (int kc = 0; kc < KLEN; kc += 32) {
        // stage X and W hi/lo (64x32 fp32 each; 2 float4 per thread per array)
        #pragma unroll
        for (int rr = 0; rr < 2; rr++) {
            int f = tid + 256 * rr;
            int m = f >> 3, c0 = (f & 7) * 4;
            float4 xv = __ldg((const float4*)&X[(size_t)(m0 + m) * ld + k_off + kc + c0]);
            float4 wv = __ldg((const float4*)&W[(size_t)m * ld + k_off + kc + c0]);
            float xx[4] = {xv.x, xv.y, xv.z, xv.w};
            float ww[4] = {wv.x, wv.y, wv.z, wv.w};
            #pragma unroll
            for (int q = 0; q < 4; q++) {
                __half h, l;
                split_f16s(xx[q], h, l);
                sX[m][c0 + q] = h; sX[m][36 + c0 + q] = l;
                split_f16s(ww[q], h, l);
                sW[m][c0 + q] = h; sW[m][36 + c0 + q] = l;
            }
        }
        __syncthreads();

        #pragma unroll
        for (int s = 0; s < 2; s++) {
            const int ac = s * 16 + 2 * tig;
            unsigned ah[4], al[4];
            ah[0] = *(const unsigned*)&sX[R + gid][ac];
            ah[1] = *(const unsigned*)&sX[R + gid + 8][ac];
            ah[2] = *(const unsigned*)&sX[R + gid][ac + 8];
            ah[3] = *(const unsigned*)&sX[R + gid + 8][ac + 8];
            al[0] = *(const unsigned*)&sX[R + gid][ac + 36];
            al[1] = *(const unsigned*)&sX[R + gid + 8][ac + 36];
            al[2] = *(const unsigned*)&sX[R + gid][ac + 44];
            al[3] = *(const unsigned*)&sX[R + gid + 8][ac + 44];
            #pragma unroll
            for (int nt = 0; nt < 4; nt++) {
                const __half* wr = sW[nh * 32 + nt * 8 + gid];
                unsigned bh[2], bl[2];
                bh[0] = *(const unsigned*)&wr[ac];
                bh[1] = *(const unsigned*)&wr[ac + 8];
                bl[0] = *(const unsigned*)&wr[ac + 36];
                bl[1] = *(const unsigned*)&wr[ac + 44];
                mma_f16(acc0[nt], ah, bh);   // hh -> acc0
                mma_f16(acc1[nt], al, bh);   // lh (x2^11) -> acc1
                mma_f16(acc1[nt], ah, bl);   // hl (x2^11) -> acc1
            }
        }
        __syncthreads();
    }

    const float inv = 1.0f / 2048.0f;
    #pragma unroll
    for (int nt = 0; nt < 4; nt++) {
        float d0 = acc0[nt][0] + acc1[nt][0] * inv;
        float d1 = acc0[nt][1] + acc1[nt][1] * inv;
        float d2 = acc0[nt][2] + acc1[nt][2] * inv;
        float d3 = acc0[nt][3] + acc1[nt][3] * inv;
        int n0 = nh * 32 + nt * 8 + 2 * tig;
        *(float2*)&outp[(size_t)(m0 + R + gid) * NE + n0]     = make_float2(d0, d1);
        *(float2*)&outp[(size_t)(m0 + R + gid + 8) * NE + n0] = make_float2(d2, d3);
    }
}

// ---------------------------------------------------------------------------
// Top-2 + softmax + per-expert list build.
// ---------------------------------------------------------------------------
__global__ __launch_bounds__(256) void top2_kernel(
    const float* __restrict__ lg1, const float* __restrict__ lg2)
{
    const int t    = blockIdx.x * 8 + (threadIdx.x >> 5);
    const int lane = threadIdx.x & 31;
    float v0 = lg1[(size_t)t * NE + lane];
    float v1 = lg1[(size_t)t * NE + lane + 32];
    if (lg2) {
        v0 += lg2[(size_t)t * NE + lane];
        v1 += lg2[(size_t)t * NE + lane + 32];
    }

    float m1; int i1;
    if (v0 >= v1) { m1 = v0; i1 = lane; } else { m1 = v1; i1 = lane + 32; }
    #pragma unroll
    for (int off = 16; off > 0; off >>= 1) {
        float om = __shfl_xor_sync(0xffffffffu, m1, off);
        int   oi = __shfl_xor_sync(0xffffffffu, i1, off);
        if (om > m1 || (om == m1 && oi < i1)) { m1 = om; i1 = oi; }
    }
    float c0 = (lane == i1)      ? -INFINITY : v0;
    float c1 = (lane + 32 == i1) ? -INFINITY : v1;
    float m2; int i2;
    if (c0 >= c1) { m2 = c0; i2 = lane; } else { m2 = c1; i2 = lane + 32; }
    #pragma unroll
    for (int off = 16; off > 0; off >>= 1) {
        float om = __shfl_xor_sync(0xffffffffu, m2, off);
        int   oi = __shfl_xor_sync(0xffffffffu, i2, off);
        if (om > m2 || (om == m2 && oi < i2)) { m2 = om; i2 = oi; }
    }
    if (lane == 0) {
        float p1 = 1.f / (1.f + expf(m2 - m1));
        g_prob[2 * t]     = p1;
        g_prob[2 * t + 1] = 1.f - p1;
        int pos = atomicAdd(&g_cnt[i1], 1);
        g_list[i1 * NPAIR + pos] = 2 * t;
        pos = atomicAdd(&g_cnt[i2], 1);
        g_list[i2 * NPAIR + pos] = 2 * t + 1;
    }
}

__global__ void prefix_kernel()
{
    __shared__ int s_c[NE];
    __shared__ int s_off[NE];
    const int e = threadIdx.x;
    int c = (g_cnt[e] + TPB - 1) / TPB;
    s_c[e] = c;
    __syncthreads();
    if (e == 0) {
        int s = 0;
        for (int i = 0; i < NE; i++) { s_off[i] = s; s += s_c[i]; }
        g_nchunks = s;
    }
    __syncthreads();
    int o = s_off[e];
    for (int i = 0; i < c; i++)
        g_chunk[o + i] = make_int2(e, i * TPB);
}

// ---------------------------------------------------------------------------
// Up bilinear, bf16 3-product, DUAL-PIPELINE (R15, best measured).
// ---------------------------------------------------------------------------
__global__ __launch_bounds__(256) void bilinear_up(
    const float* __restrict__ x, const float* __restrict__ A, const float* __restrict__ B)
{
    const int b = blockIdx.x;
    if (b >= g_nchunks) return;
    const int2 ch   = g_chunk[b];
    const int e     = ch.x;
    const int start = ch.y;
    const int cnt   = g_cnt[e];
    const int tid   = threadIdx.x;
    const int lane  = tid & 31;
    const int warp  = tid >> 5;
    const int gid   = lane >> 2;    // 0..7
    const int tig   = lane & 3;     // 0..3

    __shared__ __align__(16) __nv_bfloat16 sA[64][72];     // A-op: [o][ihi 0-31 | ilo 36-67]
    __shared__ __align__(16) __nv_bfloat16 sB[64][72];     // B-op: [p][jhi | jlo]
    __shared__ __align__(16) __nv_bfloat16 sXT[2][32][72]; // B-op: [j][ihi | ilo]  (X^T)
    __shared__ __align__(16) __nv_bfloat16 sT[2][64][72];  // A-op: [o][jhi | jlo]

    // stage A_up[e] (64x32) and B_up[e] (64x32) hi/lo  (block-wide, once)
    {
        const float4* a4 = (const float4*)(A + (size_t)e * 2048);
        const float4* b4 = (const float4*)(B + (size_t)e * 2048);
        #pragma unroll
        for (int rr = 0; rr < 2; rr++) {
            int f = tid + 256 * rr;
            int row = f >> 3, c0 = (f & 7) * 4;
            float4 av = __ldg(&a4[f]);
            float4 bv = __ldg(&b4[f]);
            float aa[4] = {av.x, av.y, av.z, av.w};
            float bb[4] = {bv.x, bv.y, bv.z, bv.w};
            #pragma unroll
            for (int q = 0; q < 4; q++) {
                __nv_bfloat16 h, l;
                split_bf16(aa[q], h, l);
                sA[row][c0 + q] = h; sA[row][36 + c0 + q] = l;
                split_bf16(bb[q], h, l);
                sB[row][c0 + q] = h; sB[row][36 + c0 + q] = l;
            }
        }
    }
    __syncthreads();   // the ONLY block-wide sync

    const int pl     = warp >> 2;      // pipeline/group 0 or 1
    const int bar    = pl + 1;         // named barrier id
    const int tid128 = tid & 127;
    const int mt     = warp & 3;       // m-tile within group
    const int R      = mt * 16;

    // group pl processes pairs start+pl, start+pl+2, ...
    for (int u = pl; u < TPB; u += 2) {
        int pi = start + u;
        if (pi >= cnt) break;                  // group-uniform
        int pair = g_list[e * NPAIR + pi];
        int t    = pair >> 1;

        // ---- stage this group's X^T hi/lo (128 threads, 2 float4 each) ----
        #pragma unroll
        for (int rr = 0; rr < 2; rr++) {
            int f = tid128 + 128 * rr;
            int i = f >> 3, j0 = (f & 7) * 4;
            float4 xv = __ldg((const float4*)&x[(size_t)t * 1024 + f * 4]);
            float vv[4] = {xv.x, xv.y, xv.z, xv.w};
            #pragma unroll
            for (int q = 0; q < 4; q++) {
                __nv_bfloat16 h, l;
                split_bf16(vv[q], h, l);
                sXT[pl][j0 + q][i]      = h;
                sXT[pl][j0 + q][36 + i] = l;
            }
        }
        bar_group(bar);

        // ---- T phase: D[64,32], 2 k-chunks x 3 products ----
        {
            float d[4][4];
            #pragma unroll
            for (int nt = 0; nt < 4; nt++)
                #pragma unroll
                for (int q = 0; q < 4; q++) d[nt][q] = 0.f;
            #pragma unroll
            for (int kc = 0; kc < 2; kc++) {
                const int ac = kc * 16 + 2 * tig;
                unsigned ah[4], al[4];
                ah[0] = *(const unsigned*)&sA[R + gid][ac];
                ah[1] = *(const unsigned*)&sA[R + gid + 8][ac];
                ah[2] = *(const unsigned*)&sA[R + gid][ac + 8];
                ah[3] = *(const unsigned*)&sA[R + gid + 8][ac + 8];
                al[0] = *(const unsigned*)&sA[R + gid][ac + 36];
                al[1] = *(const unsigned*)&sA[R + gid + 8][ac + 36];
                al[2] = *(const unsigned*)&sA[R + gid][ac + 44];
                al[3] = *(const unsigned*)&sA[R + gid + 8][ac + 44];
                #pragma unroll
                for (int nt = 0; nt < 4; nt++) {
                    const __nv_bfloat16* xr = sXT[pl][nt * 8 + gid];
                    unsigned bh[2], bl[2];
                    bh[0] = *(const unsigned*)&xr[ac];
                    bh[1] = *(const unsigned*)&xr[ac + 8];
                    bl[0] = *(const unsigned*)&xr[ac + 36];
                    bl[1] = *(const unsigned*)&xr[ac + 44];
                    mma_bf16(d[nt], ah, bh);
                    mma_bf16(d[nt], al, bh);
                    mma_bf16(d[nt], ah, bl);
                }
            }
            // store T hi/lo
            #pragma unroll
            for (int nt = 0; nt < 4; nt++) {
                int col = nt * 8 + 2 * tig;
                __nv_bfloat16 h0, l0, h1, l1;
                split_bf16(d[nt][0], h0, l0);
                split_bf16(d[nt][1], h1, l1);
                *(__nv_bfloat162*)&sT[pl][R + gid][col]      = __halves2bfloat162(h0, h1);
                *(__nv_bfloat162*)&sT[pl][R + gid][col + 36] = __halves2bfloat162(l0, l1);
                split_bf16(d[nt][2], h0, l0);
                split_bf16(d[nt][3], h1, l1);
                *(__nv_bfloat162*)&sT[pl][R + gid + 8][col]      = __halves2bfloat162(h0, h1);
                *(__nv_bfloat162*)&sT[pl][R + gid + 8][col + 36] = __halves2bfloat162(l0, l1);
            }
        }
        bar_group(bar);

        // ---- Y phase: D[64,64], 2 k-chunks x 3 products ----
        {
            float y[8][4];
            #pragma unroll
            for (int nt = 0; nt < 8; nt++)
                #pragma unroll
                for (int q = 0; q < 4; q++) y[nt][q] = 0.f;
            #pragma unroll
            for (int kc = 0; kc < 2; kc++) {
                const int ac = kc * 16 + 2 * tig;
                unsigned ah[4], al[4];
                ah[0] = *(const unsigned*)&sT[pl][R + gid][ac];
                ah[1] = *(const unsigned*)&sT[pl][R + gid + 8][ac];
                ah[2] = *(const unsigned*)&sT[pl][R + gid][ac + 8];
                ah[3] = *(const unsigned*)&sT[pl][R + gid + 8][ac + 8];
                al[0] = *(const unsigned*)&sT[pl][R + gid][ac + 36];
                al[1] = *(const unsigned*)&sT[pl][R + gid + 8][ac + 36];
                al[2] = *(const unsigned*)&sT[pl][R + gid][ac + 44];
                al[3] = *(const unsigned*)&sT[pl][R + gid + 8][ac + 44];
                #pragma unroll
                for (int nt = 0; nt < 8; nt++) {
                    const __nv_bfloat16* br = sB[nt * 8 + gid];
                    unsigned bh[2], bl[2];
                    bh[0] = *(const unsigned*)&br[ac];
                    bh[1] = *(const unsigned*)&br[ac + 8];
                    bl[0] = *(const unsigned*)&br[ac + 36];
                    bl[1] = *(const unsigned*)&br[ac + 44];
                    mma_bf16(y[nt], ah, bh);
                    mma_bf16(y[nt], al, bh);
                    mma_bf16(y[nt], ah, bl);
                }
            }
            float* yo = &g_yup[(size_t)pair * 4096];
            #pragma unroll
            for (int nt = 0; nt < 8; nt++) {
                int col = nt * 8 + 2 * tig;
                *(float2*)&yo[(R + gid) * 64 + col]     = make_float2(y[nt][0], y[nt][1]);
                *(float2*)&yo[(R + gid + 8) * 64 + col] = make_float2(y[nt][2], y[nt][3]);
            }
        }
        bar_group(bar);   // protect sXT/sT before next iteration's staging
    }
}

// ---------------------------------------------------------------------------
// Down bilinear, bf16 3-product (R10, passing).
// ---------------------------------------------------------------------------
__global__ __launch_bounds__(256) void bilinear_down(
    const float* __restrict__ A, const float* __restrict__ B)
{
    const int b = blockIdx.x;
    if (b >= g_nchunks) return;
    const int2 ch   = g_chunk[b];
    const int e     = ch.x;
    const int start = ch.y;
    const int cnt   = g_cnt[e];
    const int tid   = threadIdx.x;
    const int lane  = tid & 31;
    const int warp  = tid >> 5;
    const int gid   = lane >> 2;
    const int tig   = lane & 3;

    __shared__ __align__(16) __nv_bfloat16 sA[32][136];   // A-op: [o][ihi 0-63 | ilo 68-131]
    __shared__ __align__(16) __nv_bfloat16 sB[32][136];   // B-op: [p][jhi | jlo]
    __shared__ __align__(16) __nv_bfloat16 sHT[64][136];  // B-op: [j][ihi | ilo]  (H^T)
    __shared__ __align__(16) __nv_bfloat16 sT[32][136];   // A-op: [o][jhi | jlo]

    // stage A_down[e] (32x64), B_down[e] (32x64) hi/lo
    {
        const float4* a4 = (const float4*)(A + (size_t)e * 2048);
        const float4* b4 = (const float4*)(B + (size_t)e * 2048);
        #pragma unroll
        for (int rr = 0; rr < 2; rr++) {
            int f = tid + 256 * rr;
            int row = f >> 4, c0 = (f & 15) * 4;
            float4 av = __ldg(&a4[f]);
            float4 bv = __ldg(&b4[f]);
            float aa[4] = {av.x, av.y, av.z, av.w};
            float bb[4] = {bv.x, bv.y, bv.z, bv.w};
            #pragma unroll
            for (int q = 0; q < 4; q++) {
                __nv_bfloat16 h, l;
                split_bf16(aa[q], h, l);
                sA[row][c0 + q] = h; sA[row][68 + c0 + q] = l;
                split_bf16(bb[q], h, l);
                sB[row][c0 + q] = h; sB[row][68 + c0 + q] = l;
            }
        }
    }

    for (int u = 0; u < TPB; u++) {
        int pi = start + u;
        if (pi >= cnt) break;
        int pair = g_list[e * NPAIR + pi];
        int t    = pair >> 1;

        // ---- stage H^T hi/lo ----
        {
            const float4* h4 = (const float4*)&g_h[(size_t)t * 4096];
            #pragma unroll
            for (int rr = 0; rr < 4; rr++) {
                int f = tid + 256 * rr;
                int i = f >> 4, j0 = (f & 15) * 4;
                float4 hv = __ldg(&h4[f]);
                float vv[4] = {hv.x, hv.y, hv.z, hv.w};
                #pragma unroll
                for (int q = 0; q < 4; q++) {
                    __nv_bfloat16 h, l;
                    split_bf16(vv[q], h, l);
                    sHT[j0 + q][i]      = h;
                    sHT[j0 + q][68 + i] = l;
                }
            }
        }
        __syncthreads();

        // ---- T phase: M=32 (mt=warp&1), N=64 (2 n-tiles/warp), 4 k-chunks ----
        {
            const int mt  = warp & 1;
            const int ntb = (warp >> 1) * 2;
            const int R   = mt * 16;
            float d[2][4];
            #pragma unroll
            for (int nn = 0; nn < 2; nn++)
                #pragma unroll
                for (int q = 0; q < 4; q++) d[nn][q] = 0.f;
            #pragma unroll
            for (int kc = 0; kc < 4; kc++) {
                const int ac = kc * 16 + 2 * tig;
                unsigned ah[4], al[4];
                ah[0] = *(const unsigned*)&sA[R + gid][ac];
                ah[1] = *(const unsigned*)&sA[R + gid + 8][ac];
                ah[2] = *(const unsigned*)&sA[R + gid][ac + 8];
                ah[3] = *(const unsigned*)&sA[R + gid + 8][ac + 8];
                al[0] = *(const unsigned*)&sA[R + gid][ac + 68];
                al[1] = *(const unsigned*)&sA[R + gid + 8][ac + 68];
                al[2] = *(const unsigned*)&sA[R + gid][ac + 76];
                al[3] = *(const unsigned*)&sA[R + gid + 8][ac + 76];
                #pragma unroll
                for (int nn = 0; nn < 2; nn++) {
                    const __nv_bfloat16* hr = sHT[(ntb + nn) * 8 + gid];
                    unsigned bh[2], bl[2];
                    bh[0] = *(const unsigned*)&hr[ac];
                    bh[1] = *(const unsigned*)&hr[ac + 8];
                    bl[0] = *(const unsigned*)&hr[ac + 68];
                    bl[1] = *(const unsigned*)&hr[ac + 76];
                    mma_bf16(d[nn], ah, bh);
                    mma_bf16(d[nn], al, bh);
                    mma_bf16(d[nn], ah, bl);
                }
            }
            #pragma unroll
            for (int nn = 0; nn < 2; nn++) {
                int col = (ntb + nn) * 8 + 2 * tig;
                __nv_bfloat16 h0, l0, h1, l1;
                split_bf16(d[nn][0], h0, l0);
                split_bf16(d[nn][1], h1, l1);
                *(__nv_bfloat162*)&sT[R + gid][col]      = __halves2bfloat162(h0, h1);
                *(__nv_bfloat162*)&sT[R + gid][col + 68] = __halves2bfloat162(l0, l1);
                split_bf16(d[nn][2], h0, l0);
                split_bf16(d[nn][3], h1, l1);
                *(__nv_bfloat162*)&sT[R + gid + 8][col]      = __halves2bfloat162(h0, h1);
                *(__nv_bfloat162*)&sT[R + gid + 8][col + 68] = __halves2bfloat162(l0, l1);
            }
        }
        __syncthreads();

        // ---- Y phase: M=32, N=32, 1 tile/warp, 4 k-chunks ----
        {
            const int mt = warp & 1;
            const int nt = warp >> 1;
            const int R  = mt * 16;
            float y[4] = {0.f, 0.f, 0.f, 0.f};
            #pragma unroll
            for (int kc = 0; kc < 4; kc++) {
                const int ac = kc * 16 + 2 * tig;
                unsigned ah[4], al[4];
                ah[0] = *(const unsigned*)&sT[R + gid][ac];
                ah[1] = *(const unsigned*)&sT[R + gid + 8][ac];
                ah[2] = *(const unsigned*)&sT[R + gid][ac + 8];
                ah[3] = *(const unsigned*)&sT[R + gid + 8][ac + 8];
                al[0] = *(const unsigned*)&sT[R + gid][ac + 68];
                al[1] = *(const unsigned*)&sT[R + gid + 8][ac + 68];
                al[2] = *(const unsigned*)&sT[R + gid][ac + 76];
                al[3] = *(const unsigned*)&sT[R + gid + 8][ac + 76];
                const __nv_bfloat16* br = sB[nt * 8 + gid];
                unsigned bh[2], bl[2];
                bh[0] = *(const unsigned*)&br[ac];
                bh[1] = *(const unsigned*)&br[ac + 8];
                bl[0] = *(const unsigned*)&br[ac + 68];
                bl[1] = *(const unsigned*)&br[ac + 76];
                mma_bf16(y, ah, bh);
                mma_bf16(y, al, bh);
                mma_bf16(y, ah, bl);
            }
            float* yo = &g_ydown[(size_t)pair * 1024];
            int col = nt * 8 + 2 * tig;
            *(float2*)&yo[(R + gid) * 32 + col]     = make_float2(y[0], y[1]);
            *(float2*)&yo[(R + gid + 8) * 32 + col] = make_float2(y[2], y[3]);
        }
        __syncthreads();
    }
}

// ---------------------------------------------------------------------------
// Combine kernels
// ---------------------------------------------------------------------------
__global__ __launch_bounds__(256) void combine_up(
    const float* __restrict__ scale, const float* __restrict__ bias)
{
    const int t   = blockIdx.x;
    const int tid = threadIdx.x;
    const float p0 = g_prob[2 * t], p1 = g_prob[2 * t + 1];
    const float s  = __ldg(scale);
    const float4* y0 = (const float4*)&g_yup[(size_t)(2 * t) * 4096];
    const float4* y1 = (const float4*)&g_yup[(size_t)(2 * t + 1) * 4096];
    const float4* b4 = (const float4*)bias;
    float4* h4 = (float4*)&g_h[(size_t)t * 4096];
    #pragma unroll
    for (int rr = 0; rr < 4; rr++) {
        int f = tid + 256 * rr;
        float4 a = __ldg(&y0[f]), c = __ldg(&y1[f]), bb = __ldg(&b4[f]);
        float4 v;
        v.x = gelu_erf(s * (p0 * a.x + p1 * c.x) + bb.x);
        v.y = gelu_erf(s * (p0 * a.y + p1 * c.y) + bb.y);
        v.z = gelu_erf(s * (p0 * a.z + p1 * c.z) + bb.z);
        v.w = gelu_erf(s * (p0 * a.w + p1 * c.w) + bb.w);
        h4[f] = v;
    }
}

__global__ __launch_bounds__(256) void combine_down(
    const float* __restrict__ scale, const float* __restrict__ bias,
    float* __restrict__ out)
{
    const int t   = blockIdx.x;
    const int tid = threadIdx.x;
    const float p0 = g_prob[2 * t], p1 = g_prob[2 * t + 1];
    const float s  = __ldg(scale);
    const float4* y0 = (const float4*)&g_ydown[(size_t)(2 * t) * 1024];
    const float4* y1 = (const float4*)&g_ydown[(size_t)(2 * t + 1) * 1024];
    const float4* b4 = (const float4*)bias;
    float4 a = __ldg(&y0[tid]), c = __ldg(&y1[tid]), bb = __ldg(&b4[tid]);
    float4 v;
    v.x = s * (p0 * a.x + p1 * c.x) + bb.x;
    v.y = s * (p0 * a.y + p1 * c.y) + bb.y;
    v.z = s * (p0 * a.z + p1 * c.z) + bb.z;
    v.w = s * (p0 * a.w + p1 * c.w) + bb.w;
    ((float4*)&out[(size_t)t * 1024])[tid] = v;
}

// ---------------------------------------------------------------------------
extern "C" void kernel_launch(void* const* d_in, const int* in_sizes, int n_in,
                              void* d_out, int out_size)
{
    const float* x          = (const float*)d_in[0];
    const float* W_up       = (const float*)d_in[1];
    const float* A_up       = (const float*)d_in[2];
    const float* B_up       = (const float*)d_in[3];
    const float* scale_up   = (const float*)d_in[4];
    const float* bias_up    = (const float*)d_in[5];
    const float* W_down     = (const float*)d_in[6];
    const float* A_down     = (const float*)d_in[7];
    const float* B_down     = (const float*)d_in[8];
    const float* scale_down = (const float*)d_in[9];
    const float* bias_down  = (const float*)d_in[10];
    float*       out        = (float*)d_out;

    const int n_tok = in_sizes[0] / 1024;     // 8192

    float *h_ptr = nullptr, *lg1 = nullptr, *lg2 = nullptr;
    cudaGetSymbolAddress((void**)&h_ptr, g_h);
    cudaGetSymbolAddress((void**)&lg1, g_logits);
    cudaGetSymbolAddress((void**)&lg2, g_logits2);

    // ---- up ----
    router_f16<1024, 1><<<n_tok / 64, 256>>>(x, W_up, lg1, nullptr, 1024);
    top2_kernel<<<n_tok / 8, 256>>>(lg1, nullptr);
    prefix_kernel<<<1, 64>>>();
    bilinear_up<<<MAXCHUNK, 256>>>(x, A_up, B_up);
    combine_up<<<n_tok, 256>>>(scale_up, bias_up);

    // ---- down (K split in 2 within one 256-block launch) ----
    router_f16<2048, 2><<<2 * (n_tok / 64), 256>>>(h_ptr, W_down, lg1, lg2, 4096);
    top2_kernel<<<n_tok / 8, 256>>>(lg1, lg2);
    prefix_kernel<<<1, 64>>>();
    bilinear_down<<<MAXCHUNK, 256>>>(A_down, B_down);
    combine_down<<<n_tok, 256>>>(scale_down, bias_down, out);
}